// round 9
// baseline (speedup 1.0000x reference)
#include <cuda_runtime.h>
#include <math.h>
#include <float.h>

#define NB 32
#define NQ 900
#define NT 300
#define NC 256

#define W_CLASS 1.0f
#define W_BBOX  5.0f
#define W_GIOU  2.0f
#define W_CUTIN 2.0f

#define SCALE_F 17179869184.0f      // 2^34
#define PBIAS   (1ULL << 62)
#define BIGKEY  (1ULL << 45)
#define AUC_CAP 24
#define LSA_THREADS 512
#define LSA_WARPS   16

// Scratch (allocation-free rule: __device__ globals)
__device__ float g_CT[(size_t)NB * NT * NQ];          // transposed cost [b][t][q]
__device__ float g_E[(size_t)NB * NC * NQ];           // softmax probs [b][c][q]
__device__ unsigned long long g_rowmin[NB * NT];      // packed (fix<<11|col)+bias

__device__ __forceinline__ long long f2fix(float x) {
    return __float2ll_rn(x * SCALE_F);
}

// ---------------------------------------------------------------------------
// Kernel 1: fused softmax + transpose. Block = (b, 32-q tile), 256 threads.
// Each warp computes softmax for 4 q rows (256 classes via 2 float4 loads),
// stages probs in smem [c][qloc], then writes E[b][c][q] coalesced.
// Also re-initializes g_rowmin (graph replay safety).
// ---------------------------------------------------------------------------
__global__ void __launch_bounds__(256)
prob_kernel(const float* __restrict__ logits) {
    const int b  = blockIdx.y;
    const int q0 = blockIdx.x << 5;
    const int tid  = threadIdx.x;
    const int w    = tid >> 5;
    const int lane = tid & 31;

    __shared__ float S[NC][33];

    if (blockIdx.x == 0)
        for (int i = tid; i < NT; i += 256) g_rowmin[b * NT + i] = ~0ULL;

#pragma unroll
    for (int it = 0; it < 4; it++) {
        int ql = (w << 2) + it;
        int q  = q0 + ql;
        if (q < NQ) {
            const float4* row4 =
                reinterpret_cast<const float4*>(logits + ((size_t)b * NQ + q) * NC);
            float4 a = row4[lane];
            float4 bb = row4[lane + 32];
            float m = fmaxf(fmaxf(fmaxf(a.x, a.y), fmaxf(a.z, a.w)),
                            fmaxf(fmaxf(bb.x, bb.y), fmaxf(bb.z, bb.w)));
#pragma unroll
            for (int o = 16; o; o >>= 1)
                m = fmaxf(m, __shfl_xor_sync(0xffffffffu, m, o));
            float e0 = expf(a.x - m), e1 = expf(a.y - m);
            float e2 = expf(a.z - m), e3 = expf(a.w - m);
            float f0 = expf(bb.x - m), f1 = expf(bb.y - m);
            float f2 = expf(bb.z - m), f3 = expf(bb.w - m);
            float s = e0 + e1 + e2 + e3 + f0 + f1 + f2 + f3;
#pragma unroll
            for (int o = 16; o; o >>= 1) s += __shfl_xor_sync(0xffffffffu, s, o);
            float inv = 1.0f / s;
            int c0 = lane << 2;
            S[c0 + 0][ql] = e0 * inv;
            S[c0 + 1][ql] = e1 * inv;
            S[c0 + 2][ql] = e2 * inv;
            S[c0 + 3][ql] = e3 * inv;
            S[c0 + 128][ql] = f0 * inv;
            S[c0 + 129][ql] = f1 * inv;
            S[c0 + 130][ql] = f2 * inv;
            S[c0 + 131][ql] = f3 * inv;
        }
    }
    __syncthreads();

    int q = q0 + lane;
    if (q < NQ) {
        for (int c = w; c < NC; c += 8)
            g_E[((size_t)b * NC + c) * NQ + q] = S[c][lane];
    }
}

// ---------------------------------------------------------------------------
// Kernel 2: cost matrix. Block (32,8): tx = q in tile, 4 t's per thread.
// E read coalesced (fixed label per warp). g_CT written directly coalesced;
// out written via smem tile transpose. Row minima via warp shfl + atomicMin.
// ---------------------------------------------------------------------------
__global__ void __launch_bounds__(256)
cost_fused_kernel(const float* __restrict__ pboxes,
                  const float* __restrict__ pcut,
                  const int*   __restrict__ tlab,
                  const float* __restrict__ tboxes,
                  const float* __restrict__ tcut,
                  float* __restrict__ out) {
    const int b  = blockIdx.z;
    const int t0 = blockIdx.x << 5;
    const int q0 = blockIdx.y << 5;

    __shared__ float s_tb[4][32];
    __shared__ int   s_lab[32];
    __shared__ float s_tc[32];
    __shared__ float s_pb[4][32];
    __shared__ float s_pc[32];
    __shared__ float tile[32][33];     // [tloc][qloc]

    const int tx = threadIdx.x, ty = threadIdx.y;
    const int tid = ty * 32 + tx;

    if (tid < 32) {
        int t = t0 + tid;
        if (t < NT) {
            const float* tb = tboxes + (((size_t)b * NT + t) << 2);
            s_tb[0][tid] = tb[0]; s_tb[1][tid] = tb[1];
            s_tb[2][tid] = tb[2]; s_tb[3][tid] = tb[3];
            s_lab[tid] = tlab[b * NT + t];
            s_tc[tid]  = tcut[b * NT + t];
        }
    } else if (tid < 64) {
        int l = tid - 32; int q = q0 + l;
        if (q < NQ) {
            const float* pb = pboxes + (((size_t)b * NQ + q) << 2);
            s_pb[0][l] = pb[0]; s_pb[1][l] = pb[1];
            s_pb[2][l] = pb[2]; s_pb[3][l] = pb[3];
        }
    } else if (tid < 96) {
        int l = tid - 64; int q = q0 + l;
        if (q < NQ) s_pc[l] = pcut[b * NQ + q];
    }
    __syncthreads();

    const int q = q0 + tx;
    const bool qvalid = q < NQ;
    float px0 = s_pb[0][tx], py0 = s_pb[1][tx];
    float px1 = s_pb[2][tx], py1 = s_pb[3][tx];
    float pcv = s_pc[tx];
    float area_p = (px1 - px0) * (py1 - py0);

#pragma unroll
    for (int r = 0; r < 4; r++) {
        int tl = ty + 8 * r;
        int t  = t0 + tl;
        bool valid = qvalid && (t < NT);
        float cost = 0.f;
        if (valid) {
            float tbx0 = s_tb[0][tl], tby0 = s_tb[1][tl];
            float tbx1 = s_tb[2][tl], tby1 = s_tb[3][tl];
            float prob = g_E[((size_t)b * NC + s_lab[tl]) * NQ + q];

            float cost_bbox = fabsf(px0 - tbx0) + fabsf(py0 - tby0) +
                              fabsf(px1 - tbx1) + fabsf(py1 - tby1);
            float area_t = (tbx1 - tbx0) * (tby1 - tby0);
            float iw = fminf(px1, tbx1) - fmaxf(px0, tbx0);
            float ih = fminf(py1, tby1) - fmaxf(py0, tby0);
            float inter = fmaxf(iw, 0.f) * fmaxf(ih, 0.f);
            float uni = area_p + area_t - inter;
            float iou = inter / uni;
            float ew = fmaxf(px1, tbx1) - fminf(px0, tbx0);
            float eh = fmaxf(py1, tby1) - fminf(py0, tby0);
            float enc = fmaxf(ew, 0.f) * fmaxf(eh, 0.f);
            float giou = iou - (enc - uni) / enc;
            float ccut = fabsf(pcv - s_tc[tl]);

            cost = W_BBOX * cost_bbox - W_CLASS * prob
                 - W_GIOU * giou + W_CUTIN * ccut;
            g_CT[((size_t)b * NT + t) * NQ + q] = cost;   // coalesced
        }
        tile[tl][tx] = cost;

        // per-(b,t) packed min over this warp's 32 q's
        unsigned long long pk = valid
            ? (unsigned long long)(f2fix(cost) * 2048LL + (long long)(q + 1)) + PBIAS
            : ~0ULL;
#pragma unroll
        for (int o = 16; o; o >>= 1) {
            unsigned long long ov = __shfl_down_sync(0xffffffffu, pk, o);
            if (ov < pk) pk = ov;
        }
        if (tx == 0 && t < NT && pk != ~0ULL)
            atomicMin(&g_rowmin[b * NT + t], pk);
    }
    __syncthreads();

    // out[b][q][t] writes: lanes = t now (coalesced over t)
    int t = t0 + tx;
#pragma unroll
    for (int r = 0; r < 4; r++) {
        int ql = ty + 8 * r;
        int q2 = q0 + ql;
        if (q2 < NQ && t < NT)
            out[((size_t)b * NQ + q2) * NT + t] = tile[tx][ql];
    }
}

// ---------------------------------------------------------------------------
// Kernel 3: parallel greedy + parallel auction rounds + exact int64 Dijkstra
// residue. One CTA/batch, 512 threads (16 warps), 2 columns/thread in Dijkstra.
// (unchanged from the 147.5us version)
// ---------------------------------------------------------------------------
__global__ void __launch_bounds__(LSA_THREADS, 1)
lsa_kernel(float* __restrict__ outq, float* __restrict__ outt) {
    const int b = blockIdx.x;
    const int tid = threadIdx.x;
    const int warp = tid >> 5;
    const int lane = tid & 31;

    __shared__ long long u_s[NT + 1];
    __shared__ long long v_s[NQ + 1];
    __shared__ int p_s[NQ + 1];
    __shared__ int way_s[NQ + 1];
    __shared__ unsigned long long colslot[NQ + 1];
    __shared__ unsigned long long red[3][LSA_WARPS];
    __shared__ int flist[NT];
    __shared__ long long bid_d[NT], bid_u2[NT];
    __shared__ int bid_j[NT];
    __shared__ int amin[NT + 1];
    __shared__ int colclaim[NQ + 1];
    __shared__ int s_nf, s_live, s_nd;

    long long d[2];
    const int base = tid * 2 + 1;
    const bool owner = base <= NQ;
    const long long INF = 1LL << 60;

    for (int j = tid; j <= NQ; j += LSA_THREADS) {
        p_s[j] = 0; v_s[j] = 0; colclaim[j] = 0x7fffffff;
    }
    for (int i = tid; i < NT; i += LSA_THREADS) {
        long long pk = (long long)(g_rowmin[b * NT + i] - PBIAS);
        u_s[i + 1] = pk >> 11;
        amin[i + 1] = (int)(pk & 2047);
    }
    if (tid < 3 * LSA_WARPS) red[tid / LSA_WARPS][tid % LSA_WARPS] = ~0ULL;
    if (tid == 0) { u_s[0] = 0; s_nf = 0; }
    __syncthreads();

    // ---- Phase 1: parallel greedy (column goes to smallest claiming row) ----
    for (int i = tid + 1; i <= NT; i += LSA_THREADS)
        atomicMin(&colclaim[amin[i]], i);
    __syncthreads();
    for (int i = tid + 1; i <= NT; i += LSA_THREADS) {
        int j = amin[i];
        if (colclaim[j] == i) p_s[j] = i;
        else flist[atomicAdd(&s_nf, 1)] = i;
    }
    __syncthreads();
    if (tid == 0) s_live = s_nf;
    __syncthreads();

    const float* __restrict__ Cb = g_CT + (size_t)b * NT * NQ;
    const int nf0 = s_nf;

    // ---- Phase 2: parallel auction rounds (batched ART) ----
    for (int round = 0; round < AUC_CAP; round++) {
        __syncthreads();
        if (s_live == 0) break;

        for (int j = tid; j <= NQ; j += LSA_THREADS) colslot[j] = ~0ULL;
        __syncthreads();

        for (int fi = warp; fi < nf0; fi += LSA_WARPS) {
            int row = flist[fi];
            if (row == 0) continue;
            const float* crow = Cb + (size_t)(row - 1) * NQ;

            unsigned long long t1 = ~0ULL, t2 = ~0ULL;
#pragma unroll
            for (int k = 0; k < 8; k++) {
                int f4 = lane + (k << 5);
                if (f4 < NQ / 4) {
                    float4 cf = reinterpret_cast<const float4*>(crow)[f4];
                    int col0 = f4 * 4 + 1;
                    long long ci[4] = {f2fix(cf.x), f2fix(cf.y),
                                       f2fix(cf.z), f2fix(cf.w)};
#pragma unroll
                    for (int c = 0; c < 4; c++) {
                        long long rc = ci[c] - v_s[col0 + c];
                        unsigned long long pk =
                            (unsigned long long)(rc * 2048LL +
                                                 (long long)(col0 + c)) + PBIAS;
                        if (pk < t1) { t2 = t1; t1 = pk; }
                        else if (pk < t2) t2 = pk;
                    }
                }
            }
#pragma unroll
            for (int o = 16; o; o >>= 1) {
                unsigned long long o1 = __shfl_down_sync(0xffffffffu, t1, o);
                unsigned long long o2 = __shfl_down_sync(0xffffffffu, t2, o);
                if (lane + o < 32) {
                    unsigned long long lo = t1 < o1 ? t1 : o1;
                    unsigned long long hi = t1 < o1 ? o1 : t1;
                    unsigned long long m2 = t2 < o2 ? t2 : o2;
                    t2 = hi < m2 ? hi : m2;
                    t1 = lo;
                }
            }
            if (lane == 0) {
                long long p1 = (long long)(t1 - PBIAS);
                long long p2 = (long long)(t2 - PBIAS);
                long long u1v = p1 >> 11, u2v = p2 >> 11;
                int j1 = (int)(p1 & 2047), j2 = (int)(p2 & 2047);
                long long delta = u2v - u1v;
                int jb = j1;
                if (delta == 0 && p_s[j1] != 0 && p_s[j2] == 0) jb = j2;
                bid_j[fi] = jb;
                bid_d[fi] = delta;
                bid_u2[fi] = u2v;
                unsigned long long key =
                    ((BIGKEY - (unsigned long long)delta) << 10) | (unsigned)fi;
                atomicMin(&colslot[jb], key);
            }
        }
        __syncthreads();

        for (int fi = tid; fi < nf0; fi += LSA_THREADS) {
            int row = flist[fi];
            if (row == 0) continue;
            int jb = bid_j[fi];
            if ((int)(colslot[jb] & 1023u) == fi) {
                int prev = p_s[jb];
                p_s[jb] = row;
                u_s[row] = bid_u2[fi];
                v_s[jb] -= bid_d[fi];
                if (prev > 0) flist[fi] = prev;
                else { flist[fi] = 0; atomicSub(&s_live, 1); }
            }
        }
    }
    __syncthreads();

    // gather residue for exact Dijkstra
    if (tid == 0) {
        int n = 0;
        for (int fi = 0; fi < nf0; fi++)
            if (flist[fi]) flist[n++] = flist[fi];
        s_nd = n;
    }
    __syncthreads();

    // ---- Phase 3: exact Dijkstra (shortest augmenting path) for residue ----
    const int nd = s_nd;
    int par = 0;
    for (int fi = 0; fi < nd; fi++) {
        d[0] = INF; d[1] = INF;
        unsigned usedm = 0;
        if (tid == 0) p_s[0] = flist[fi];
        __syncthreads();

        int j0 = 0;
        long long delta = 0;
        while (true) {
            int row = p_s[j0];
            long long k = delta - u_s[row];

            int rel = j0 - base;
            if (rel >= 0 && rel < 2) usedm |= 1u << rel;

            unsigned long long lmin = ~0ULL;
            if (owner) {
                float2 cf = *reinterpret_cast<const float2*>(
                    Cb + (size_t)(row - 1) * NQ + (base - 1));
                long long ci[2] = {f2fix(cf.x), f2fix(cf.y)};
#pragma unroll
                for (int c = 0; c < 2; c++) {
                    if (!((usedm >> c) & 1u)) {
                        long long alt = k + ci[c] - v_s[base + c];
                        if (alt < d[c]) { d[c] = alt; way_s[base + c] = j0; }
                        unsigned long long pk =
                            (unsigned long long)(d[c] * 2048LL +
                                                 (long long)(base + c)) + PBIAS;
                        if (pk < lmin) lmin = pk;
                    }
                }
            }
            int nxt = par + 1; if (nxt == 3) nxt = 0;
            if (lane == 0) red[nxt][warp] = ~0ULL;
            if (lmin != ~0ULL) atomicMin(&red[par][warp], lmin);
            __syncthreads();

            unsigned long long m = red[par][0];
#pragma unroll
            for (int w = 1; w < LSA_WARPS; w++) {
                unsigned long long x = red[par][w];
                if (x < m) m = x;
            }
            par = nxt;
            long long pks = (long long)(m - PBIAS);
            delta = pks >> 11;
            j0 = (int)(pks & 2047);
            if (p_s[j0] == 0) break;
        }

        const long long dstar = delta;
        if (owner) {
#pragma unroll
            for (int c = 0; c < 2; c++) {
                if ((usedm >> c) & 1u) {
                    v_s[base + c] += d[c] - dstar;
                    u_s[p_s[base + c]] += dstar - d[c];
                }
            }
        }
        if (tid == 0) u_s[p_s[0]] += dstar;
        __syncthreads();
        if (tid == 0) {
            int jj = j0;
            while (jj) { int j1 = way_s[jj]; p_s[jj] = p_s[j1]; jj = j1; }
        }
    }
    __syncthreads();

    for (int j = tid + 1; j <= NQ; j += LSA_THREADS) {
        int r = p_s[j];
        if (r > 0) outq[b * NT + (r - 1)] = (float)(j - 1);
    }
    for (int t = tid; t < NT; t += LSA_THREADS) outt[b * NT + t] = (float)t;
}

// ---------------------------------------------------------------------------
extern "C" void kernel_launch(void* const* d_in, const int* in_sizes, int n_in,
                              void* d_out, int out_size) {
    const float* logits = (const float*)d_in[0];
    const float* pboxes = (const float*)d_in[1];
    const float* pcut   = (const float*)d_in[2];
    const int*   tlab   = (const int*)d_in[3];
    const float* tboxes = (const float*)d_in[4];
    const float* tcut   = (const float*)d_in[5];
    float* out = (float*)d_out;

    dim3 pgrid((NQ + 31) / 32, NB);
    prob_kernel<<<pgrid, 256>>>(logits);

    dim3 cgrid((NT + 31) / 32, (NQ + 31) / 32, NB);
    cost_fused_kernel<<<cgrid, dim3(32, 8)>>>(pboxes, pcut, tlab,
                                              tboxes, tcut, out);

    float* outq = out + (size_t)NB * NQ * NT;
    float* outt = outq + (size_t)NB * NT;
    lsa_kernel<<<NB, LSA_THREADS>>>(outq, outt);
}

// round 10
// speedup vs baseline: 1.0327x; 1.0327x over previous
#include <cuda_runtime.h>
#include <math.h>
#include <float.h>

#define NB 32
#define NQ 900
#define NT 300
#define NC 256
#define QT 29                       // ceil(NQ/32) q-tiles

#define W_CLASS 1.0f
#define W_BBOX  5.0f
#define W_GIOU  2.0f
#define W_CUTIN 2.0f

#define SCALE_F 17179869184.0f      // 2^34
#define PBIAS   (1ULL << 62)
#define BIGKEY  (1ULL << 45)
#define AUC_CAP 24
#define LSA_THREADS 512
#define LSA_WARPS   16

// Scratch (allocation-free rule: __device__ globals)
__device__ float g_CT[(size_t)NB * NT * NQ];              // transposed cost [b][t][q]
__device__ unsigned long long g_pmin[(size_t)NB * NT * QT]; // per-(b,t,qtile) packed min

__device__ __forceinline__ long long f2fix(float x) {
    return __float2ll_rn(x * SCALE_F);
}

// ---------------------------------------------------------------------------
// Kernel 1 (single fused preprocessing kernel): block = (q-tile, b).
// In-block softmax for 32 q's (probs stay in smem), then all 300 t's:
// cost to g_CT (coalesced, lanes=q), out via tile transpose (lanes=t),
// per-(t,qtile) packed row minima to g_pmin (race-free, no init pass).
// ---------------------------------------------------------------------------
__global__ void __launch_bounds__(256)
cost_fused_kernel(const float* __restrict__ logits,
                  const float* __restrict__ pboxes,
                  const float* __restrict__ pcut,
                  const int*   __restrict__ tlab,
                  const float* __restrict__ tboxes,
                  const float* __restrict__ tcut,
                  float* __restrict__ out) {
    const int qt = blockIdx.x;
    const int b  = blockIdx.y;
    const int q0 = qt << 5;
    const int tid = threadIdx.x;
    const int tx = tid & 31;        // lane: q within tile (compute), t (drain)
    const int ty = tid >> 5;        // warp

    __shared__ float S[32][NC + 1];         // probs [qloc][class]
    __shared__ float s_tx0[NT], s_ty0[NT], s_tx1[NT], s_ty1[NT];
    __shared__ float s_tc[NT];
    __shared__ int   s_lab[NT];
    __shared__ float s_pb[4][32], s_pc[32];
    __shared__ float tile[32][33];          // [tloc][qloc]

    // target data for all 300 t's
    for (int t = tid; t < NT; t += 256) {
        float4 tb = reinterpret_cast<const float4*>(tboxes)[(size_t)b * NT + t];
        s_tx0[t] = tb.x; s_ty0[t] = tb.y; s_tx1[t] = tb.z; s_ty1[t] = tb.w;
        s_lab[t] = tlab[b * NT + t];
        s_tc[t]  = tcut[b * NT + t];
    }
    if (tid < 32) {
        int q = q0 + tid;
        if (q < NQ) {
            float4 pb = reinterpret_cast<const float4*>(pboxes)[(size_t)b * NQ + q];
            s_pb[0][tid] = pb.x; s_pb[1][tid] = pb.y;
            s_pb[2][tid] = pb.z; s_pb[3][tid] = pb.w;
            s_pc[tid] = pcut[b * NQ + q];
        }
    }

    // in-block softmax: warp ty handles q-locals 4*ty .. 4*ty+3
#pragma unroll
    for (int it = 0; it < 4; it++) {
        int ql = (ty << 2) + it;
        int q  = q0 + ql;
        if (q < NQ) {
            const float4* row4 =
                reinterpret_cast<const float4*>(logits + ((size_t)b * NQ + q) * NC);
            float4 a = row4[tx];
            float4 bb = row4[tx + 32];
            float m = fmaxf(fmaxf(fmaxf(a.x, a.y), fmaxf(a.z, a.w)),
                            fmaxf(fmaxf(bb.x, bb.y), fmaxf(bb.z, bb.w)));
#pragma unroll
            for (int o = 16; o; o >>= 1)
                m = fmaxf(m, __shfl_xor_sync(0xffffffffu, m, o));
            float e0 = expf(a.x - m), e1 = expf(a.y - m);
            float e2 = expf(a.z - m), e3 = expf(a.w - m);
            float f0 = expf(bb.x - m), f1 = expf(bb.y - m);
            float f2 = expf(bb.z - m), f3 = expf(bb.w - m);
            float s = e0 + e1 + e2 + e3 + f0 + f1 + f2 + f3;
#pragma unroll
            for (int o = 16; o; o >>= 1) s += __shfl_xor_sync(0xffffffffu, s, o);
            float inv = 1.0f / s;
            int c0 = tx << 2;
            S[ql][c0 + 0] = e0 * inv; S[ql][c0 + 1] = e1 * inv;
            S[ql][c0 + 2] = e2 * inv; S[ql][c0 + 3] = e3 * inv;
            S[ql][c0 + 128] = f0 * inv; S[ql][c0 + 129] = f1 * inv;
            S[ql][c0 + 130] = f2 * inv; S[ql][c0 + 131] = f3 * inv;
        }
    }
    __syncthreads();

    const int q = q0 + tx;
    const bool qvalid = q < NQ;
    float px0 = s_pb[0][tx], py0 = s_pb[1][tx];
    float px1 = s_pb[2][tx], py1 = s_pb[3][tx];
    float pcv = s_pc[tx];
    float area_p = (px1 - px0) * (py1 - py0);

    for (int tt = 0; tt < NT; tt += 32) {
#pragma unroll
        for (int r = 0; r < 4; r++) {
            int tl = ty + 8 * r;
            int t  = tt + tl;
            bool valid = qvalid && (t < NT);
            float cost = 0.f;
            if (valid) {
                float tbx0 = s_tx0[t], tby0 = s_ty0[t];
                float tbx1 = s_tx1[t], tby1 = s_ty1[t];
                float prob = S[tx][s_lab[t]];       // lanes: stride NC+1, conflict-free

                float cost_bbox = fabsf(px0 - tbx0) + fabsf(py0 - tby0) +
                                  fabsf(px1 - tbx1) + fabsf(py1 - tby1);
                float area_t = (tbx1 - tbx0) * (tby1 - tby0);
                float iw = fminf(px1, tbx1) - fmaxf(px0, tbx0);
                float ih = fminf(py1, tby1) - fmaxf(py0, tby0);
                float inter = fmaxf(iw, 0.f) * fmaxf(ih, 0.f);
                float uni = area_p + area_t - inter;
                float iou = inter / uni;
                float ew = fmaxf(px1, tbx1) - fminf(px0, tbx0);
                float eh = fmaxf(py1, tby1) - fminf(py0, tby0);
                float enc = fmaxf(ew, 0.f) * fmaxf(eh, 0.f);
                float giou = iou - (enc - uni) / enc;
                float ccut = fabsf(pcv - s_tc[t]);

                cost = W_BBOX * cost_bbox - W_CLASS * prob
                     - W_GIOU * giou + W_CUTIN * ccut;
                g_CT[((size_t)b * NT + t) * NQ + q] = cost;   // coalesced (lanes=q)
            }
            tile[tl][tx] = cost;

            unsigned long long pk = valid
                ? (unsigned long long)(f2fix(cost) * 2048LL + (long long)(q + 1)) + PBIAS
                : ~0ULL;
#pragma unroll
            for (int o = 16; o; o >>= 1) {
                unsigned long long ov = __shfl_down_sync(0xffffffffu, pk, o);
                if (ov < pk) pk = ov;
            }
            if (tx == 0 && t < NT)
                g_pmin[((size_t)b * NT + t) * QT + qt] = pk;   // race-free
        }
        __syncthreads();

        int t = tt + tx;                       // lanes = t for out drain
#pragma unroll
        for (int r = 0; r < 4; r++) {
            int ql = ty + 8 * r;
            int q2 = q0 + ql;
            if (q2 < NQ && t < NT)
                out[((size_t)b * NQ + q2) * NT + t] = tile[tx][ql];
        }
        __syncthreads();
    }
}

// ---------------------------------------------------------------------------
// Kernel 2: parallel greedy + parallel auction rounds + exact int64 Dijkstra
// residue. One CTA/batch, 512 threads. Identical to the 147.5us version
// except row-min init now reduces g_pmin (no global atomics / init pass).
// ---------------------------------------------------------------------------
__global__ void __launch_bounds__(LSA_THREADS, 1)
lsa_kernel(float* __restrict__ outq, float* __restrict__ outt) {
    const int b = blockIdx.x;
    const int tid = threadIdx.x;
    const int warp = tid >> 5;
    const int lane = tid & 31;

    __shared__ long long u_s[NT + 1];
    __shared__ long long v_s[NQ + 1];
    __shared__ int p_s[NQ + 1];
    __shared__ int way_s[NQ + 1];
    __shared__ unsigned long long colslot[NQ + 1];
    __shared__ unsigned long long red[3][LSA_WARPS];
    __shared__ int flist[NT];
    __shared__ long long bid_d[NT], bid_u2[NT];
    __shared__ int bid_j[NT];
    __shared__ int amin[NT + 1];
    __shared__ int colclaim[NQ + 1];
    __shared__ int s_nf, s_live, s_nd;

    long long d[2];
    const int base = tid * 2 + 1;
    const bool owner = base <= NQ;
    const long long INF = 1LL << 60;

    for (int j = tid; j <= NQ; j += LSA_THREADS) {
        p_s[j] = 0; v_s[j] = 0; colclaim[j] = 0x7fffffff;
    }
    for (int i = tid; i < NT; i += LSA_THREADS) {
        const unsigned long long* pm = g_pmin + ((size_t)b * NT + i) * QT;
        unsigned long long m = pm[0];
#pragma unroll 4
        for (int k = 1; k < QT; k++) {
            unsigned long long x = pm[k];
            if (x < m) m = x;
        }
        long long pk = (long long)(m - PBIAS);
        u_s[i + 1] = pk >> 11;
        amin[i + 1] = (int)(pk & 2047);
    }
    if (tid < 3 * LSA_WARPS) red[tid / LSA_WARPS][tid % LSA_WARPS] = ~0ULL;
    if (tid == 0) { u_s[0] = 0; s_nf = 0; }
    __syncthreads();

    // ---- Phase 1: parallel greedy (column goes to smallest claiming row) ----
    for (int i = tid + 1; i <= NT; i += LSA_THREADS)
        atomicMin(&colclaim[amin[i]], i);
    __syncthreads();
    for (int i = tid + 1; i <= NT; i += LSA_THREADS) {
        int j = amin[i];
        if (colclaim[j] == i) p_s[j] = i;
        else flist[atomicAdd(&s_nf, 1)] = i;
    }
    __syncthreads();
    if (tid == 0) s_live = s_nf;
    __syncthreads();

    const float* __restrict__ Cb = g_CT + (size_t)b * NT * NQ;
    const int nf0 = s_nf;

    // ---- Phase 2: parallel auction rounds (batched ART) ----
    for (int round = 0; round < AUC_CAP; round++) {
        __syncthreads();
        if (s_live == 0) break;

        for (int j = tid; j <= NQ; j += LSA_THREADS) colslot[j] = ~0ULL;
        __syncthreads();

        for (int fi = warp; fi < nf0; fi += LSA_WARPS) {
            int row = flist[fi];
            if (row == 0) continue;
            const float* crow = Cb + (size_t)(row - 1) * NQ;

            unsigned long long t1 = ~0ULL, t2 = ~0ULL;
#pragma unroll
            for (int k = 0; k < 8; k++) {
                int f4 = lane + (k << 5);
                if (f4 < NQ / 4) {
                    float4 cf = reinterpret_cast<const float4*>(crow)[f4];
                    int col0 = f4 * 4 + 1;
                    long long ci[4] = {f2fix(cf.x), f2fix(cf.y),
                                       f2fix(cf.z), f2fix(cf.w)};
#pragma unroll
                    for (int c = 0; c < 4; c++) {
                        long long rc = ci[c] - v_s[col0 + c];
                        unsigned long long pk =
                            (unsigned long long)(rc * 2048LL +
                                                 (long long)(col0 + c)) + PBIAS;
                        if (pk < t1) { t2 = t1; t1 = pk; }
                        else if (pk < t2) t2 = pk;
                    }
                }
            }
#pragma unroll
            for (int o = 16; o; o >>= 1) {
                unsigned long long o1 = __shfl_down_sync(0xffffffffu, t1, o);
                unsigned long long o2 = __shfl_down_sync(0xffffffffu, t2, o);
                if (lane + o < 32) {
                    unsigned long long lo = t1 < o1 ? t1 : o1;
                    unsigned long long hi = t1 < o1 ? o1 : t1;
                    unsigned long long m2 = t2 < o2 ? t2 : o2;
                    t2 = hi < m2 ? hi : m2;
                    t1 = lo;
                }
            }
            if (lane == 0) {
                long long p1 = (long long)(t1 - PBIAS);
                long long p2 = (long long)(t2 - PBIAS);
                long long u1v = p1 >> 11, u2v = p2 >> 11;
                int j1 = (int)(p1 & 2047), j2 = (int)(p2 & 2047);
                long long delta = u2v - u1v;
                int jb = j1;
                if (delta == 0 && p_s[j1] != 0 && p_s[j2] == 0) jb = j2;
                bid_j[fi] = jb;
                bid_d[fi] = delta;
                bid_u2[fi] = u2v;
                unsigned long long key =
                    ((BIGKEY - (unsigned long long)delta) << 10) | (unsigned)fi;
                atomicMin(&colslot[jb], key);
            }
        }
        __syncthreads();

        for (int fi = tid; fi < nf0; fi += LSA_THREADS) {
            int row = flist[fi];
            if (row == 0) continue;
            int jb = bid_j[fi];
            if ((int)(colslot[jb] & 1023u) == fi) {
                int prev = p_s[jb];
                p_s[jb] = row;
                u_s[row] = bid_u2[fi];
                v_s[jb] -= bid_d[fi];
                if (prev > 0) flist[fi] = prev;
                else { flist[fi] = 0; atomicSub(&s_live, 1); }
            }
        }
    }
    __syncthreads();

    // gather residue for exact Dijkstra
    if (tid == 0) {
        int n = 0;
        for (int fi = 0; fi < nf0; fi++)
            if (flist[fi]) flist[n++] = flist[fi];
        s_nd = n;
    }
    __syncthreads();

    // ---- Phase 3: exact Dijkstra (shortest augmenting path) for residue ----
    const int nd = s_nd;
    int par = 0;
    for (int fi = 0; fi < nd; fi++) {
        d[0] = INF; d[1] = INF;
        unsigned usedm = 0;
        if (tid == 0) p_s[0] = flist[fi];
        __syncthreads();

        int j0 = 0;
        long long delta = 0;
        while (true) {
            int row = p_s[j0];
            long long k = delta - u_s[row];

            int rel = j0 - base;
            if (rel >= 0 && rel < 2) usedm |= 1u << rel;

            unsigned long long lmin = ~0ULL;
            if (owner) {
                float2 cf = *reinterpret_cast<const float2*>(
                    Cb + (size_t)(row - 1) * NQ + (base - 1));
                long long ci[2] = {f2fix(cf.x), f2fix(cf.y)};
#pragma unroll
                for (int c = 0; c < 2; c++) {
                    if (!((usedm >> c) & 1u)) {
                        long long alt = k + ci[c] - v_s[base + c];
                        if (alt < d[c]) { d[c] = alt; way_s[base + c] = j0; }
                        unsigned long long pk =
                            (unsigned long long)(d[c] * 2048LL +
                                                 (long long)(base + c)) + PBIAS;
                        if (pk < lmin) lmin = pk;
                    }
                }
            }
            int nxt = par + 1; if (nxt == 3) nxt = 0;
            if (lane == 0) red[nxt][warp] = ~0ULL;
            if (lmin != ~0ULL) atomicMin(&red[par][warp], lmin);
            __syncthreads();

            unsigned long long m = red[par][0];
#pragma unroll
            for (int w = 1; w < LSA_WARPS; w++) {
                unsigned long long x = red[par][w];
                if (x < m) m = x;
            }
            par = nxt;
            long long pks = (long long)(m - PBIAS);
            delta = pks >> 11;
            j0 = (int)(pks & 2047);
            if (p_s[j0] == 0) break;
        }

        const long long dstar = delta;
        if (owner) {
#pragma unroll
            for (int c = 0; c < 2; c++) {
                if ((usedm >> c) & 1u) {
                    v_s[base + c] += d[c] - dstar;
                    u_s[p_s[base + c]] += dstar - d[c];
                }
            }
        }
        if (tid == 0) u_s[p_s[0]] += dstar;
        __syncthreads();
        if (tid == 0) {
            int jj = j0;
            while (jj) { int j1 = way_s[jj]; p_s[jj] = p_s[j1]; jj = j1; }
        }
    }
    __syncthreads();

    for (int j = tid + 1; j <= NQ; j += LSA_THREADS) {
        int r = p_s[j];
        if (r > 0) outq[b * NT + (r - 1)] = (float)(j - 1);
    }
    for (int t = tid; t < NT; t += LSA_THREADS) outt[b * NT + t] = (float)t;
}

// ---------------------------------------------------------------------------
extern "C" void kernel_launch(void* const* d_in, const int* in_sizes, int n_in,
                              void* d_out, int out_size) {
    const float* logits = (const float*)d_in[0];
    const float* pboxes = (const float*)d_in[1];
    const float* pcut   = (const float*)d_in[2];
    const int*   tlab   = (const int*)d_in[3];
    const float* tboxes = (const float*)d_in[4];
    const float* tcut   = (const float*)d_in[5];
    float* out = (float*)d_out;

    dim3 cgrid(QT, NB);
    cost_fused_kernel<<<cgrid, 256>>>(logits, pboxes, pcut, tlab,
                                      tboxes, tcut, out);

    float* outq = out + (size_t)NB * NQ * NT;
    float* outt = outq + (size_t)NB * NT;
    lsa_kernel<<<NB, LSA_THREADS>>>(outq, outt);
}